// round 9
// baseline (speedup 1.0000x reference)
#include <cuda_runtime.h>
#include <cuda_bf16.h>
#include <cstdint>

#define B_   4096
#define HID  512
#define NR   32
#define T_   32
#define NLOG 832          // logit cols padded to 13*64 (805 meaningful)
#define BG   32768        // B_*G
#define KTOT 1536         // 3*512 split-bf16 stacking
#define BM   128
#define BN   64
#define KC   64
#define NCHUNK (KTOT / KC)   // 24
#define APAD 72              // smem row length in bf16 (144B, conflict-free ldmatrix)
#define NBUF 4

// ---------------- scratch (device globals: no allocations allowed) ----------------
__device__ __nv_bfloat16 g_Ab[(size_t)B_ * KTOT];      // [m][k]  (hi,hi,lo)
__device__ __nv_bfloat16 g_Bb[(size_t)NLOG * KTOT];    // [n][k]  (hi,lo,hi)
__device__ float g_logits[(size_t)B_ * NLOG];          // z @ W_cat
__device__ float g_Rf[(size_t)BG * NR];                // [bg][r]
__device__ float g_step[(size_t)T_ * BG * 8];          // [t][bg][opw0..3,dd,d1,d2,act]

__device__ __forceinline__ float sigm(float x) {
    return __fdividef(1.f, 1.f + __expf(-x));
}
__device__ __forceinline__ float dec5(const float* __restrict__ p, float dg) {
    float v = 0.f;
#pragma unroll
    for (int j = 0; j < 5; j++) v += sigm(p[j] + dg) * (float)(1 << j);
    return v;
}

__device__ __forceinline__ uint32_t s2u(const void* p) {
    uint32_t a;
    asm("{ .reg .u64 t; cvta.to.shared.u64 t, %1; cvt.u32.u64 %0, t; }" : "=r"(a) : "l"(p));
    return a;
}
__device__ __forceinline__ void cpasync16(uint32_t saddr, const void* g) {
    asm volatile("cp.async.cg.shared.global [%0], [%1], 16;" :: "r"(saddr), "l"(g));
}
__device__ __forceinline__ void ldsm4(uint32_t* r, uint32_t addr) {
    asm volatile("ldmatrix.sync.aligned.m8n8.x4.shared.b16 {%0,%1,%2,%3}, [%4];"
                 : "=r"(r[0]), "=r"(r[1]), "=r"(r[2]), "=r"(r[3]) : "r"(addr));
}
__device__ __forceinline__ void mma16816(float* c, const uint32_t* a, const uint32_t* b) {
    asm volatile(
        "mma.sync.aligned.m16n8k16.row.col.f32.bf16.bf16.f32 "
        "{%0,%1,%2,%3}, {%4,%5,%6,%7}, {%8,%9}, {%0,%1,%2,%3};"
        : "+f"(c[0]), "+f"(c[1]), "+f"(c[2]), "+f"(c[3])
        : "r"(a[0]), "r"(a[1]), "r"(a[2]), "r"(a[3]), "r"(b[0]), "r"(b[1]));
}

// ---------------- kernel: pack A = [hi(z), hi(z), lo(z)] bf16, [m][k] ----------------
__global__ void pack_a_kernel(const float* __restrict__ Z) {
    int idx = blockIdx.x * blockDim.x + threadIdx.x;     // B_*KTOT
    int m = idx / KTOT, k = idx - m * KTOT;
    __nv_bfloat16 o;
    if (k < 1024) {
        o = __float2bfloat16(Z[(size_t)m * 512 + (k & 511)]);
    } else {
        float v = Z[(size_t)m * 512 + (k - 1024)];
        __nv_bfloat16 hi = __float2bfloat16(v);
        o = __float2bfloat16(v - __bfloat162float(hi));
    }
    g_Ab[idx] = o;
}

// ---------------- kernel: pack B = [hi(W), lo(W), hi(W)] bf16, [n][k] ----------------
__global__ void pack_b_kernel(const float* __restrict__ wR,  const float* __restrict__ wOp,
                              const float* __restrict__ wD,  const float* __restrict__ wS1,
                              const float* __restrict__ wS2, const float* __restrict__ wL) {
    int idx = blockIdx.x * blockDim.x + threadIdx.x;     // NLOG*KTOT
    int n = idx / KTOT, k = idx - n * KTOT;
    int kr = (k < 1024) ? (k & 511) : (k - 1024);
    float v = 0.f;
    if      (n < 256) v = wR [kr * 256 + n];
    else if (n < 320) v = wOp[kr * 64  + (n - 256)];
    else if (n < 480) v = wD [kr * 160 + (n - 320)];
    else if (n < 640) v = wS1[kr * 160 + (n - 480)];
    else if (n < 800) v = wS2[kr * 160 + (n - 640)];
    else if (n < 805) v = wL [kr * 5   + (n - 800)];
    __nv_bfloat16 hi = __float2bfloat16(v);
    __nv_bfloat16 o;
    if (k < 512)       o = hi;
    else if (k < 1024) o = __float2bfloat16(v - __bfloat162float(hi));  // lo
    else               o = hi;
    g_Bb[idx] = o;
}

// ---------------- kernel: mma.sync GEMM, 4-stage cp.async pipeline ----------------
// block 128x64, 8 warps (4x2), warp tile 32x32, KC=64, NBUF=4.
__global__ __launch_bounds__(256) void gemm_mma() {
    extern __shared__ char sm[];
    const int tid  = threadIdx.x;
    const int lane = tid & 31, warp = tid >> 5;
    const int wm = warp & 3, wn = warp >> 2;
    const int bm = blockIdx.y * BM, bn = blockIdx.x * BN;

    // smem: A[NBUF][128][APAD], B[NBUF][64][APAD] bf16
    const uint32_t ASZ = BM * APAD * 2;          // 18432
    const uint32_t BSZ = BN * APAD * 2;          // 9216
    const uint32_t BBASE = NBUF * ASZ;           // 73728
    const uint32_t sbase = s2u(sm);

    const __nv_bfloat16* Ag = g_Ab + (size_t)bm * KTOT;
    const __nv_bfloat16* Bg = g_Bb + (size_t)bn * KTOT;

    float acc[2][4][4];
#pragma unroll
    for (int mt = 0; mt < 2; mt++)
#pragma unroll
        for (int nt = 0; nt < 4; nt++)
#pragma unroll
            for (int j = 0; j < 4; j++) acc[mt][nt][j] = 0.f;

#define LOAD_CHUNK(c, buf)                                                          \
    {                                                                               \
        _Pragma("unroll")                                                           \
        for (int i = 0; i < 4; i++) {                                               \
            int idx = tid + i * 256, r = idx >> 3, s = idx & 7;                     \
            cpasync16(sbase + (buf) * ASZ + (uint32_t)(r * (APAD * 2) + s * 16),    \
                      Ag + (size_t)r * KTOT + (c) * KC + s * 8);                    \
        }                                                                           \
        _Pragma("unroll")                                                           \
        for (int i = 0; i < 2; i++) {                                               \
            int idx = tid + i * 256, r = idx >> 3, s = idx & 7;                     \
            cpasync16(sbase + BBASE + (buf) * BSZ + (uint32_t)(r * (APAD * 2) + s * 16), \
                      Bg + (size_t)r * KTOT + (c) * KC + s * 8);                    \
        }                                                                           \
    }

    LOAD_CHUNK(0, 0); asm volatile("cp.async.commit_group;");
    LOAD_CHUNK(1, 1); asm volatile("cp.async.commit_group;");
    LOAD_CHUNK(2, 2); asm volatile("cp.async.commit_group;");

    for (int c = 0; c < NCHUNK; c++) {
        asm volatile("cp.async.wait_group 2;");
        __syncthreads();
        if (c + 3 < NCHUNK) LOAD_CHUNK(c + 3, (c + 3) & 3);
        asm volatile("cp.async.commit_group;");   // empty groups near tail keep counts uniform

        const int buf = c & 3;
        const uint32_t aB = sbase + buf * ASZ;
        const uint32_t bB = sbase + BBASE + buf * BSZ;
#pragma unroll
        for (int k16 = 0; k16 < 4; k16++) {
            uint32_t afr[2][4];
#pragma unroll
            for (int mt = 0; mt < 2; mt++) {
                int row = wm * 32 + mt * 16 + (lane & 15);
                uint32_t addr = aB + (uint32_t)(row * (APAD * 2) + ((lane >> 4) * 16) + k16 * 32);
                ldsm4(afr[mt], addr);
            }
            uint32_t bfr[4][2];
#pragma unroll
            for (int p = 0; p < 2; p++) {
                int row = wn * 32 + p * 16 + (lane & 7) + ((lane >> 4) * 8);
                uint32_t addr = bB + (uint32_t)(row * (APAD * 2) + (((lane >> 3) & 1) * 16) + k16 * 32);
                uint32_t t4[4];
                ldsm4(t4, addr);
                bfr[p * 2][0] = t4[0]; bfr[p * 2][1] = t4[1];
                bfr[p * 2 + 1][0] = t4[2]; bfr[p * 2 + 1][1] = t4[3];
            }
#pragma unroll
            for (int mt = 0; mt < 2; mt++)
#pragma unroll
                for (int nt = 0; nt < 4; nt++)
                    mma16816(acc[mt][nt], afr[mt], bfr[nt]);
        }
    }

#pragma unroll
    for (int mt = 0; mt < 2; mt++) {
#pragma unroll
        for (int nt = 0; nt < 4; nt++) {
            int row = bm + wm * 32 + mt * 16 + (lane >> 2);
            int col = bn + wn * 32 + nt * 8 + (lane & 3) * 2;
            float* p0 = g_logits + (size_t)row * NLOG + col;
            *(float2*)p0 = make_float2(acc[mt][nt][0], acc[mt][nt][1]);
            float* p1 = g_logits + (size_t)(row + 8) * NLOG + col;
            *(float2*)p1 = make_float2(acc[mt][nt][2], acc[mt][nt][3]);
        }
    }
#undef LOAD_CHUNK
}

// ---------------- kernel: per-step params (opw softmax, decimals, act) ----------------
__global__ void step_kernel() {
    int idx = blockIdx.x * blockDim.x + threadIdx.x;   // T*BG, bg fastest
    int bg = idx & (BG - 1);
    int t  = idx >> 15;
    int b  = bg >> 3, g = bg & 7;
    float dg = (float)g * (2.f / 7.f) - 1.f;
    const float* row = g_logits + (size_t)b * NLOG;

    float op_d = sigm(row[256 + 2 * t] + dg) + 2.f * sigm(row[256 + 2 * t + 1] + dg);
    float dd   = dec5(row + 320 + 5 * t, dg);
    float d1   = dec5(row + 480 + 5 * t, dg);
    float d2   = dec5(row + 640 + 5 * t, dg);
    float plen = dec5(row + 800, dg);
    float act  = sigm(plen - (float)t - 0.5f);

    float e0 = __expf(-op_d * op_d);
    float p1 = op_d - 1.f; float e1 = __expf(-p1 * p1);
    float p2 = op_d - 2.f; float e2 = __expf(-p2 * p2);
    float p3 = op_d - 3.f; float e3 = __expf(-p3 * p3);
    float inv = __fdividef(1.f, e0 + e1 + e2 + e3);

    float4* o = (float4*)(g_step + ((size_t)t * BG + bg) * 8);
    o[0] = make_float4(e0 * inv, e1 * inv, e2 * inv, e3 * inv);
    o[1] = make_float4(dd, d1, d2, act);
}

// ---------------- kernel: 32-step soft-VM scan, 4 lanes per (b,g), R0 fused ----------------
__global__ __launch_bounds__(128) void scan_kernel() {
    const int t4 = blockIdx.x * 128 + threadIdx.x;     // BG*4 threads
    const int bg = t4 >> 2, q = t4 & 3;
    const int b = bg >> 3, g = bg & 7;
    const float dg = (float)g * (2.f / 7.f) - 1.f;
    const int s0 = q * 8;                              // this lane's slots s0..s0+7

    // fused R0: decode this lane's 8 registers from logits
    const float* lr = g_logits + (size_t)b * NLOG + s0 * 8;
    float r[8], m[8];
#pragma unroll
    for (int j = 0; j < 8; j++) {
        float v = 0.f;
#pragma unroll
        for (int jb = 0; jb < 8; jb++)
            v += sigm(lr[j * 8 + jb] + dg) * (float)(1 << jb);
        r[j] = v; m[j] = 0.f;
    }

    for (int t = 0; t < 32; t++) {
        const float4* sp = (const float4*)(g_step + ((size_t)t * BG + bg) * 8);
        float4 p0 = sp[0], p1 = sp[1];
        float ow0 = p0.x, ow1 = p0.y, ow2 = p0.z, ow3 = p0.w;
        float dd = p1.x, d1 = p1.y, d2 = p1.z, act = p1.w;

        float ed[8];
        float sd = 0.f, sa = 0.f, sb = 0.f;
        float dv = 0.f, v1 = 0.f, v2 = 0.f, lv = 0.f;
#pragma unroll
        for (int j = 0; j < 8; j++) {
            float fi = (float)(s0 + j);
            float pd = dd - fi; float e_d = __expf(-pd * pd);
            float pa = d1 - fi; float e_1 = __expf(-pa * pa);
            float pb = d2 - fi; float e_2 = __expf(-pb * pb);
            ed[j] = e_d;
            sd += e_d; sa += e_1; sb += e_2;
            dv += r[j] * e_d; v1 += r[j] * e_1; v2 += r[j] * e_2; lv += m[j] * e_1;
        }
        // quad reduction (lanes q^1, q^2 within the same bg)
#pragma unroll
        for (int off = 1; off <= 2; off <<= 1) {
            sd += __shfl_xor_sync(0xffffffffu, sd, off);
            sa += __shfl_xor_sync(0xffffffffu, sa, off);
            sb += __shfl_xor_sync(0xffffffffu, sb, off);
            dv += __shfl_xor_sync(0xffffffffu, dv, off);
            v1 += __shfl_xor_sync(0xffffffffu, v1, off);
            v2 += __shfl_xor_sync(0xffffffffu, v2, off);
            lv += __shfl_xor_sync(0xffffffffu, lv, off);
        }
        float inv_sd = __fdividef(1.f, sd);
        float inv_sa = __fdividef(1.f, sa);
        float inv_sb = __fdividef(1.f, sb);
        dv *= inv_sd; v1 *= inv_sa; v2 *= inv_sb; lv *= inv_sa;

        float res = ow0 * (v1 + v2) + ow1 * (v1 - v2) + ow2 * lv + ow3 * dv;
        float grs = act * (ow0 + ow1 + ow2) * inv_sd;
        float gms = act * ow3 * inv_sd;
#pragma unroll
        for (int j = 0; j < 8; j++) {
            float w = ed[j];
            float gr = grs * w;
            r[j] += gr * (res - r[j]);
            float gm = gms * w;
            m[j] += gm * (v1 - m[j]);
        }
    }
    float* orow = g_Rf + (size_t)bg * 32 + s0;
    *(float4*)(orow)     = make_float4(r[0], r[1], r[2], r[3]);
    *(float4*)(orow + 4) = make_float4(r[4], r[5], r[6], r[7]);
}

// ---------------- kernel: h = Rf @ W_r2h^T + b, fused LayerNorm ----------------
__global__ __launch_bounds__(512) void final_kernel(const float* __restrict__ Wr,
                                                    const float* __restrict__ bias,
                                                    const float* __restrict__ lng,
                                                    const float* __restrict__ lnb,
                                                    float* __restrict__ out,
                                                    int rows_per_block) {
    const int c = threadIdx.x;
    const int lane = c & 31, warp = c >> 5;

    float w[32];
#pragma unroll
    for (int j = 0; j < 8; j++) {
        float4 v = *(const float4*)(Wr + (size_t)c * 32 + j * 4);
        w[4 * j] = v.x; w[4 * j + 1] = v.y; w[4 * j + 2] = v.z; w[4 * j + 3] = v.w;
    }
    const float bb = bias[c], gg = lng[c], be = lnb[c];

    __shared__ float srf[128];
    __shared__ float red[16][8];
    __shared__ float fin[8];

    const int row_base = blockIdx.x * rows_per_block;
    for (int batch = 0; batch < rows_per_block; batch += 4) {
        const int row0 = row_base + batch;
        __syncthreads();
        if (c < 128)
            srf[c] = g_Rf[(size_t)(row0 + (c & 3)) * 32 + (c >> 2)];
        __syncthreads();

        float a0 = 0.f, a1 = 0.f, a2 = 0.f, a3 = 0.f;
#pragma unroll
        for (int rIdx = 0; rIdx < 32; rIdx++) {
            float4 v = *(const float4*)&srf[rIdx * 4];
            float ww = w[rIdx];
            a0 += ww * v.x; a1 += ww * v.y; a2 += ww * v.z; a3 += ww * v.w;
        }
        float h[4] = {a0 + bb, a1 + bb, a2 + bb, a3 + bb};

        float s[8];
#pragma unroll
        for (int j = 0; j < 4; j++) { s[j] = h[j]; s[4 + j] = h[j] * h[j]; }
#pragma unroll
        for (int off = 16; off > 0; off >>= 1)
#pragma unroll
            for (int j = 0; j < 8; j++) s[j] += __shfl_xor_sync(0xffffffffu, s[j], off);
        if (lane == 0)
#pragma unroll
            for (int j = 0; j < 8; j++) red[warp][j] = s[j];
        __syncthreads();
        if (c < 8) {
            float tot = 0.f;
#pragma unroll
            for (int wi = 0; wi < 16; wi++) tot += red[wi][c];
            fin[c] = tot;
        }
        __syncthreads();
#pragma unroll
        for (int rr = 0; rr < 4; rr++) {
            float mu  = fin[rr] * (1.f / 512.f);
            float msq = fin[4 + rr] * (1.f / 512.f);
            float var = msq - mu * mu;
            float sc  = rsqrtf(var + 1e-5f);
            out[(size_t)(row0 + rr) * 512 + c] = (h[rr] - mu) * sc * gg + be;
        }
    }
}

// ---------------- launch ----------------
extern "C" void kernel_launch(void* const* d_in, const int* in_sizes, int n_in,
                              void* d_out, int out_size) {
    const float* z    = (const float*)d_in[0];
    const float* wR   = (const float*)d_in[1];
    const float* wOp  = (const float*)d_in[2];
    const float* wD   = (const float*)d_in[3];
    const float* wS1  = (const float*)d_in[4];
    const float* wS2  = (const float*)d_in[5];
    const float* wL   = (const float*)d_in[6];
    const float* wr2h = (const float*)d_in[7];
    const float* br2h = (const float*)d_in[8];
    const float* lng  = (const float*)d_in[9];
    const float* lnb  = (const float*)d_in[10];
    float* out = (float*)d_out;

    const int GEMM_SMEM = NBUF * (BM + BN) * APAD * 2;   // 110592 bytes
    cudaFuncSetAttribute(gemm_mma, cudaFuncAttributeMaxDynamicSharedMemorySize, GEMM_SMEM);

    pack_a_kernel<<<(B_ * KTOT) / 256, 256>>>(z);
    pack_b_kernel<<<(NLOG * KTOT) / 256, 256>>>(wR, wOp, wD, wS1, wS2, wL);
    gemm_mma<<<dim3(NLOG / BN, B_ / BM), 256, GEMM_SMEM>>>();
    step_kernel<<<(T_ * BG) / 256, 256>>>();
    scan_kernel<<<(BG * 4) / 128, 128>>>();
    final_kernel<<<1024, 512>>>(wr2h, br2h, lng, lnb, out, BG / 1024);
}